// round 2
// baseline (speedup 1.0000x reference)
#include <cuda_runtime.h>
#include <cuda_bf16.h>
#include <math.h>

// Problem shapes (fixed by the dataset)
#define NN      50000      // nodes
#define F_IN    512
#define F1      256        // HEADS*HID
#define HEADS   8
#define HID     32
#define NCLASS  32
#define NEG_SLOPE 0.2f

// ---------------- scratch (device globals; no allocation allowed) ----------
__device__ float g_h1  [(size_t)NN * F1];   // x @ W1            [N,256]
__device__ float g_agg1[(size_t)NN * F1];   // layer-1 aggregate [N,256]
__device__ float g_h2  [(size_t)NN * NCLASS];
__device__ float g_ssrc1[NN * HEADS];
__device__ float g_sdst1[NN * HEADS];
__device__ float g_m1  [NN * HEADS];
__device__ float g_den1[NN * HEADS];
__device__ float g_ssrc2[NN];
__device__ float g_sdst2[NN];
__device__ float g_m2  [NN];
__device__ float g_den2[NN];

// ---------------- helpers ---------------------------------------------------
__device__ __forceinline__ void atomicMaxF(float* addr, float v) {
    // exact float max via signed/unsigned int atomics (init must be -inf)
    if (v >= 0.f) atomicMax((int*)addr, __float_as_int(v));
    else          atomicMin((unsigned int*)addr, __float_as_uint(v));
}

__device__ __forceinline__ float warp_sum(float v) {
#pragma unroll
    for (int o = 16; o > 0; o >>= 1) v += __shfl_down_sync(0xffffffffu, v, o);
    return v;
}

__device__ __forceinline__ void red_add_v4(float* addr, float4 v) {
    asm volatile("red.global.add.v4.f32 [%0], {%1,%2,%3,%4};"
                 :: "l"(addr), "f"(v.x), "f"(v.y), "f"(v.z), "f"(v.w)
                 : "memory");
}

__device__ __forceinline__ float lrelu(float s) {
    return s > 0.f ? s : NEG_SLOPE * s;
}

// ---------------- init ------------------------------------------------------
__global__ void init_kernel(float* __restrict__ out, int out_sz) {
    int i = blockIdx.x * blockDim.x + threadIdx.x;
    const float NEG_INF = -__int_as_float(0x7f800000);
    if (i < NN * F1) g_agg1[i] = 0.f;
    if (i < NN * HEADS) { g_den1[i] = 0.f; g_m1[i] = NEG_INF; }
    if (i < NN)         { g_den2[i] = 0.f; g_m2[i] = NEG_INF; }
    if (i < out_sz) out[i] = 0.f;
}

// ---------------- GEMM1: g_h1 = x[ N,512 ] @ W1[512,256] -------------------
__global__ void __launch_bounds__(256)
gemm1_kernel(const float* __restrict__ A, const float* __restrict__ B) {
    __shared__ float As[8][128];
    __shared__ float Bs[8][128];
    const int M = NN, K = F_IN;
    int tid = threadIdx.x;
    int row0 = blockIdx.y * 128, col0 = blockIdx.x * 128;

    int a_r = tid >> 1, a_k = (tid & 1) * 4;         // A tile: 128 rows x 8 k
    int b_k = tid >> 5, b_c = (tid & 31) * 4;        // B tile: 8 k x 128 cols
    int tr = (tid >> 4) * 8, tc = (tid & 15) * 8;

    float acc[8][8];
#pragma unroll
    for (int i = 0; i < 8; i++)
#pragma unroll
        for (int j = 0; j < 8; j++) acc[i][j] = 0.f;

    for (int k0 = 0; k0 < K; k0 += 8) {
        float4 av = make_float4(0.f, 0.f, 0.f, 0.f);
        int gr = row0 + a_r;
        if (gr < M)
            av = *reinterpret_cast<const float4*>(A + (size_t)gr * K + k0 + a_k);
        As[a_k + 0][a_r] = av.x; As[a_k + 1][a_r] = av.y;
        As[a_k + 2][a_r] = av.z; As[a_k + 3][a_r] = av.w;

        float4 bv = *reinterpret_cast<const float4*>(
            B + (size_t)(k0 + b_k) * F1 + col0 + b_c);
        *reinterpret_cast<float4*>(&Bs[b_k][b_c]) = bv;
        __syncthreads();

#pragma unroll
        for (int kk = 0; kk < 8; kk++) {
            float ar[8], br[8];
#pragma unroll
            for (int i = 0; i < 8; i++) ar[i] = As[kk][tr + i];
#pragma unroll
            for (int j = 0; j < 8; j++) br[j] = Bs[kk][tc + j];
#pragma unroll
            for (int i = 0; i < 8; i++)
#pragma unroll
                for (int j = 0; j < 8; j++) acc[i][j] += ar[i] * br[j];
        }
        __syncthreads();
    }
#pragma unroll
    for (int i = 0; i < 8; i++) {
        int gr = row0 + tr + i;
        if (gr >= M) break;
#pragma unroll
        for (int j = 0; j < 8; j += 4) {
            float4 v = make_float4(acc[i][j], acc[i][j+1], acc[i][j+2], acc[i][j+3]);
            *reinterpret_cast<float4*>(&g_h1[(size_t)gr * F1 + col0 + tc + j]) = v;
        }
    }
}

// ---------------- per-node attention scores layer 1 -------------------------
__global__ void __launch_bounds__(256)
scores1_kernel(const float* __restrict__ asrc, const float* __restrict__ adst) {
    int n = blockIdx.x, t = threadIdx.x;      // t = head*32 + c
    float v = g_h1[(size_t)n * F1 + t];
    float ps = warp_sum(v * asrc[t]);
    float pd = warp_sum(v * adst[t]);
    if ((t & 31) == 0) {
        int h = t >> 5;
        g_ssrc1[n * HEADS + h] = ps;
        g_sdst1[n * HEADS + h] = pd;
    }
}

// ---------------- edge passes layer 1 (edge_index is int32 [2,E]) ----------
__global__ void emax1_kernel(const int* __restrict__ ei, int E, int N) {
    int idx = blockIdx.x * blockDim.x + threadIdx.x;
    int ET = E + N;
    int e = idx >> 3, h = idx & 7;
    if (e >= ET) return;
    int src, dst;
    if (e < E) { src = ei[e]; dst = ei[E + e]; } else { src = dst = e - E; }
    float val = lrelu(g_ssrc1[src * HEADS + h] + g_sdst1[dst * HEADS + h]);
    atomicMaxF(&g_m1[dst * HEADS + h], val);
}

__global__ void esum1_kernel(const int* __restrict__ ei, int E, int N) {
    int idx = blockIdx.x * blockDim.x + threadIdx.x;
    int ET = E + N;
    int e = idx >> 3, h = idx & 7;
    if (e >= ET) return;
    int src, dst;
    if (e < E) { src = ei[e]; dst = ei[E + e]; } else { src = dst = e - E; }
    float val = lrelu(g_ssrc1[src * HEADS + h] + g_sdst1[dst * HEADS + h]);
    float mv = g_m1[dst * HEADS + h]; if (!(mv > -1e30f)) mv = 0.f;
    atomicAdd(&g_den1[dst * HEADS + h], __expf(val - mv));
}

// 64 threads per edge: each handles one float4 of the 256-wide feature
__global__ void __launch_bounds__(256)
scatter1_kernel(const int* __restrict__ ei, int E, int N) {
    long long idx = (long long)blockIdx.x * blockDim.x + threadIdx.x;
    int ET = E + N;
    int e = (int)(idx >> 6);
    if (e >= ET) return;
    int t = (int)(idx & 63);     // float4 index; head = t>>3
    int h = t >> 3;
    int src, dst;
    if (e < E) { src = ei[e]; dst = ei[E + e]; } else { src = dst = e - E; }
    float s = g_ssrc1[src * HEADS + h] + g_sdst1[dst * HEADS + h];
    float val = lrelu(s);
    float mv = g_m1[dst * HEADS + h]; if (!(mv > -1e30f)) mv = 0.f;
    float alpha = __expf(val - mv) / (g_den1[dst * HEADS + h] + 1e-16f);
    float4 hv = *reinterpret_cast<const float4*>(g_h1 + (size_t)src * F1 + t * 4);
    red_add_v4(g_agg1 + (size_t)dst * F1 + t * 4,
               make_float4(alpha * hv.x, alpha * hv.y, alpha * hv.z, alpha * hv.w));
}

// ---------------- ELU(agg1 + b1) in place ----------------------------------
__global__ void elu_kernel(const float* __restrict__ b1) {
    int i = blockIdx.x * blockDim.x + threadIdx.x;
    if (i >= NN * F1) return;
    float v = g_agg1[i] + b1[i & (F1 - 1)];
    g_agg1[i] = v > 0.f ? v : expm1f(v);
}

// ---------------- GEMM2 + scores2 (warp per node) --------------------------
__global__ void __launch_bounds__(256)
gemm2_kernel(const float* __restrict__ W2, const float* __restrict__ asrc,
             const float* __restrict__ adst) {
    int w = (blockIdx.x * blockDim.x + threadIdx.x) >> 5;
    int lane = threadIdx.x & 31;
    if (w >= NN) return;
    const float* row = g_agg1 + (size_t)w * F1;
    float rv[8];
#pragma unroll
    for (int j = 0; j < 8; j++) rv[j] = row[lane + j * 32];
    float acc = 0.f;
#pragma unroll
    for (int j = 0; j < 8; j++) {
#pragma unroll
        for (int s = 0; s < 32; s++) {
            float a = __shfl_sync(0xffffffffu, rv[j], s);
            acc += a * __ldg(&W2[(j * 32 + s) * NCLASS + lane]);
        }
    }
    g_h2[(size_t)w * NCLASS + lane] = acc;
    float ps = warp_sum(acc * asrc[lane]);
    float pd = warp_sum(acc * adst[lane]);
    if (lane == 0) { g_ssrc2[w] = ps; g_sdst2[w] = pd; }
}

// ---------------- edge passes layer 2 (H=1) --------------------------------
__global__ void emax2_kernel(const int* __restrict__ ei, int E, int N) {
    int e = blockIdx.x * blockDim.x + threadIdx.x;
    if (e >= E + N) return;
    int src, dst;
    if (e < E) { src = ei[e]; dst = ei[E + e]; } else { src = dst = e - E; }
    atomicMaxF(&g_m2[dst], lrelu(g_ssrc2[src] + g_sdst2[dst]));
}

__global__ void esum2_kernel(const int* __restrict__ ei, int E, int N) {
    int e = blockIdx.x * blockDim.x + threadIdx.x;
    if (e >= E + N) return;
    int src, dst;
    if (e < E) { src = ei[e]; dst = ei[E + e]; } else { src = dst = e - E; }
    float val = lrelu(g_ssrc2[src] + g_sdst2[dst]);
    float mv = g_m2[dst]; if (!(mv > -1e30f)) mv = 0.f;
    atomicAdd(&g_den2[dst], __expf(val - mv));
}

// 8 threads per edge (8 x float4 = 32 floats)
__global__ void __launch_bounds__(256)
scatter2_kernel(const int* __restrict__ ei, int E, int N,
                float* __restrict__ out) {
    int idx = blockIdx.x * blockDim.x + threadIdx.x;
    int e = idx >> 3;
    if (e >= E + N) return;
    int t = idx & 7;
    int src, dst;
    if (e < E) { src = ei[e]; dst = ei[E + e]; } else { src = dst = e - E; }
    float val = lrelu(g_ssrc2[src] + g_sdst2[dst]);
    float mv = g_m2[dst]; if (!(mv > -1e30f)) mv = 0.f;
    float alpha = __expf(val - mv) / (g_den2[dst] + 1e-16f);
    float4 hv = *reinterpret_cast<const float4*>(g_h2 + (size_t)src * NCLASS + t * 4);
    red_add_v4(out + (size_t)dst * NCLASS + t * 4,
               make_float4(alpha * hv.x, alpha * hv.y, alpha * hv.z, alpha * hv.w));
}

// ---------------- epilogue: out += b2 + 1e-6 --------------------------------
__global__ void epi_kernel(float* __restrict__ out, const float* __restrict__ b2) {
    int i = blockIdx.x * blockDim.x + threadIdx.x;
    if (i >= NN * NCLASS) return;
    out[i] = out[i] + b2[i & (NCLASS - 1)] + 1e-6f;
}

// ---------------- launch ----------------------------------------------------
extern "C" void kernel_launch(void* const* d_in, const int* in_sizes, int n_in,
                              void* d_out, int out_size) {
    const float* x     = (const float*)d_in[0];
    const int*   ei    = (const int*)d_in[1];     // int32 [2, E]
    const float* W1    = (const float*)d_in[2];
    const float* asrc1 = (const float*)d_in[3];
    const float* adst1 = (const float*)d_in[4];
    const float* b1    = (const float*)d_in[5];
    const float* W2    = (const float*)d_in[6];
    const float* asrc2 = (const float*)d_in[7];
    const float* adst2 = (const float*)d_in[8];
    const float* b2    = (const float*)d_in[9];
    float* out = (float*)d_out;

    int N  = in_sizes[0] / F_IN;   // 50000
    int E  = in_sizes[1] / 2;      // 800000
    int ET = E + N;

    init_kernel<<<(N * F1 + 255) / 256, 256>>>(out, out_size);

    gemm1_kernel<<<dim3(F1 / 128, (N + 127) / 128), 256>>>(x, W1);
    scores1_kernel<<<N, 256>>>(asrc1, adst1);

    emax1_kernel<<<((long long)ET * 8 + 255) / 256, 256>>>(ei, E, N);
    esum1_kernel<<<((long long)ET * 8 + 255) / 256, 256>>>(ei, E, N);
    scatter1_kernel<<<(unsigned)(((long long)ET * 64 + 255) / 256), 256>>>(ei, E, N);

    elu_kernel<<<(N * F1 + 255) / 256, 256>>>(b1);

    gemm2_kernel<<<(N * 32 + 255) / 256, 256>>>(W2, asrc2, adst2);

    emax2_kernel<<<(ET + 255) / 256, 256>>>(ei, E, N);
    esum2_kernel<<<(ET + 255) / 256, 256>>>(ei, E, N);
    scatter2_kernel<<<((long long)ET * 8 + 255) / 256, 256>>>(ei, E, N, out);

    epi_kernel<<<(N * NCLASS + 255) / 256, 256>>>(out, b2);
}

// round 3
// speedup vs baseline: 1.3974x; 1.3974x over previous
#include <cuda_runtime.h>
#include <cuda_bf16.h>
#include <math.h>

// Problem shapes (fixed by the dataset)
#define NN      50000      // nodes
#define F_IN    512
#define F1      256        // HEADS*HID
#define HEADS   8
#define HID     32
#define NCLASS  32
#define NEG_SLOPE 0.2f
#define ET_MAX  (800000 + NN)

// ---------------- scratch (device globals; no allocation allowed) ----------
__device__ float g_h1  [(size_t)NN * F1];     // x @ W1            [N,256]
__device__ float g_agg1[(size_t)NN * F1];     // layer-1 aggregate [N,256]
__device__ float g_h2  [(size_t)NN * NCLASS];
__device__ float g_w1  [(size_t)ET_MAX * HEADS];  // exp(edge score) layer 1
__device__ float g_w2  [(size_t)ET_MAX];          // exp(edge score) layer 2
__device__ float g_ssrc1[NN * HEADS];
__device__ float g_sdst1[NN * HEADS];
__device__ float g_den1[NN * HEADS];          // becomes 1/(den+eps)
__device__ float g_ssrc2[NN];
__device__ float g_sdst2[NN];
__device__ float g_den2[NN];

// ---------------- helpers ---------------------------------------------------
__device__ __forceinline__ float warp_sum(float v) {
#pragma unroll
    for (int o = 16; o > 0; o >>= 1) v += __shfl_down_sync(0xffffffffu, v, o);
    return v;
}

__device__ __forceinline__ void red_add_v4(float* addr, float4 v) {
    asm volatile("red.global.add.v4.f32 [%0], {%1,%2,%3,%4};"
                 :: "l"(addr), "f"(v.x), "f"(v.y), "f"(v.z), "f"(v.w)
                 : "memory");
}

__device__ __forceinline__ float lrelu(float s) {
    return s > 0.f ? s : NEG_SLOPE * s;
}

__device__ __forceinline__ unsigned f2tf32(float f) {
    unsigned u;
    asm("cvt.rna.tf32.f32 %0, %1;" : "=r"(u) : "f"(f));
    return u;
}

__device__ __forceinline__ void mma_tf32(float* d, const unsigned* a, const unsigned* b) {
    asm volatile(
        "mma.sync.aligned.m16n8k8.row.col.f32.tf32.tf32.f32 "
        "{%0,%1,%2,%3}, {%4,%5,%6,%7}, {%8,%9}, {%0,%1,%2,%3};"
        : "+f"(d[0]), "+f"(d[1]), "+f"(d[2]), "+f"(d[3])
        : "r"(a[0]), "r"(a[1]), "r"(a[2]), "r"(a[3]), "r"(b[0]), "r"(b[1]));
}

// ---------------- init ------------------------------------------------------
__global__ void init_kernel(float* __restrict__ out, int out_sz) {
    int i = blockIdx.x * blockDim.x + threadIdx.x;
    if (i < NN * F1) g_agg1[i] = 0.f;
    if (i < NN * HEADS) g_den1[i] = 0.f;
    if (i < NN)         g_den2[i] = 0.f;
    if (i < out_sz) out[i] = 0.f;
}

// ---------------- GEMM1 (tf32 tensor cores): g_h1 = x @ W1 ------------------
// Block tile 128(M) x 64(N) x 32(K). 256 threads = 8 warps in 4x2 grid,
// warp tile 32x32 = 2(M) x 4(N) mma.m16n8k8 tiles.
__global__ void __launch_bounds__(256)
gemm1_kernel(const float* __restrict__ A, const float* __restrict__ B) {
    __shared__ unsigned As[128][36];   // padded: bank-conflict-free frag loads
    __shared__ unsigned Bs[32][72];

    const int M = NN, K = F_IN;
    int tid  = threadIdx.x;
    int lane = tid & 31, wid = tid >> 5;
    int warp_m = wid >> 1, warp_n = wid & 1;
    int row0 = blockIdx.y * 128, col0 = blockIdx.x * 64;

    int g  = lane >> 2;   // group id (0..7)
    int tg = lane & 3;    // thread in group (0..3)

    float acc[2][4][4];
#pragma unroll
    for (int i = 0; i < 2; i++)
#pragma unroll
        for (int j = 0; j < 4; j++)
#pragma unroll
            for (int r = 0; r < 4; r++) acc[i][j][r] = 0.f;

    // global->smem assignments
    int a_r = tid >> 1;                 // 0..127
    int a_c0 = (tid & 1) * 16;          // 0 or 16 (4 float4s)
    int b_r = tid >> 3;                 // 0..31
    int b_c0 = (tid & 7) * 8;           // 8 floats (2 float4s)

    for (int k0 = 0; k0 < K; k0 += 32) {
        // load A tile (zero-fill OOB rows)
        int gr = row0 + a_r;
#pragma unroll
        for (int q = 0; q < 4; q++) {
            float4 v = make_float4(0.f, 0.f, 0.f, 0.f);
            if (gr < M)
                v = *reinterpret_cast<const float4*>(A + (size_t)gr * K + k0 + a_c0 + q * 4);
            As[a_r][a_c0 + q * 4 + 0] = f2tf32(v.x);
            As[a_r][a_c0 + q * 4 + 1] = f2tf32(v.y);
            As[a_r][a_c0 + q * 4 + 2] = f2tf32(v.z);
            As[a_r][a_c0 + q * 4 + 3] = f2tf32(v.w);
        }
        // load B tile
#pragma unroll
        for (int q = 0; q < 2; q++) {
            float4 v = *reinterpret_cast<const float4*>(
                B + (size_t)(k0 + b_r) * F1 + col0 + b_c0 + q * 4);
            Bs[b_r][b_c0 + q * 4 + 0] = f2tf32(v.x);
            Bs[b_r][b_c0 + q * 4 + 1] = f2tf32(v.y);
            Bs[b_r][b_c0 + q * 4 + 2] = f2tf32(v.z);
            Bs[b_r][b_c0 + q * 4 + 3] = f2tf32(v.w);
        }
        __syncthreads();

#pragma unroll
        for (int ks = 0; ks < 4; ks++) {
            int kb = ks * 8;
            unsigned afr[2][4];
#pragma unroll
            for (int mt = 0; mt < 2; mt++) {
                int rb = warp_m * 32 + mt * 16;
                afr[mt][0] = As[rb + g    ][kb + tg    ];
                afr[mt][1] = As[rb + g + 8][kb + tg    ];
                afr[mt][2] = As[rb + g    ][kb + tg + 4];
                afr[mt][3] = As[rb + g + 8][kb + tg + 4];
            }
            unsigned bfr[4][2];
#pragma unroll
            for (int nt = 0; nt < 4; nt++) {
                int nb = warp_n * 32 + nt * 8;
                bfr[nt][0] = Bs[kb + tg    ][nb + g];
                bfr[nt][1] = Bs[kb + tg + 4][nb + g];
            }
#pragma unroll
            for (int mt = 0; mt < 2; mt++)
#pragma unroll
                for (int nt = 0; nt < 4; nt++)
                    mma_tf32(acc[mt][nt], afr[mt], bfr[nt]);
        }
        __syncthreads();
    }

    // store accumulators
#pragma unroll
    for (int mt = 0; mt < 2; mt++) {
#pragma unroll
        for (int half = 0; half < 2; half++) {
            int gr = row0 + warp_m * 32 + mt * 16 + g + half * 8;
            if (gr >= M) continue;
#pragma unroll
            for (int nt = 0; nt < 4; nt++) {
                int gc = col0 + warp_n * 32 + nt * 8 + 2 * tg;
                float2 v = make_float2(acc[mt][nt][half * 2], acc[mt][nt][half * 2 + 1]);
                *reinterpret_cast<float2*>(&g_h1[(size_t)gr * F1 + gc]) = v;
            }
        }
    }
}

// ---------------- per-node attention scores layer 1 -------------------------
__global__ void __launch_bounds__(256)
scores1_kernel(const float* __restrict__ asrc, const float* __restrict__ adst) {
    int n = blockIdx.x, t = threadIdx.x;      // t = head*32 + c
    float v = g_h1[(size_t)n * F1 + t];
    float ps = warp_sum(v * asrc[t]);
    float pd = warp_sum(v * adst[t]);
    if ((t & 31) == 0) {
        int h = t >> 5;
        g_ssrc1[n * HEADS + h] = ps;
        g_sdst1[n * HEADS + h] = pd;
    }
}

// ---------------- edge pass layer 1: w = exp(lrelu(score)), den += w --------
__global__ void __launch_bounds__(256)
esum1_kernel(const int* __restrict__ ei, int E, int N) {
    long long idx = (long long)blockIdx.x * blockDim.x + threadIdx.x;
    int ET = E + N;
    int e = (int)(idx >> 3), h = (int)(idx & 7);
    if (e >= ET) return;
    int src, dst;
    if (e < E) { src = ei[e]; dst = ei[E + e]; } else { src = dst = e - E; }
    float s = g_ssrc1[src * HEADS + h] + g_sdst1[dst * HEADS + h];
    float w = __expf(lrelu(s));
    g_w1[(size_t)e * HEADS + h] = w;
    atomicAdd(&g_den1[dst * HEADS + h], w);
}

__global__ void invden1_kernel() {
    int i = blockIdx.x * blockDim.x + threadIdx.x;
    if (i < NN * HEADS) g_den1[i] = __frcp_rn(g_den1[i] + 1e-16f);
}

// ---------------- scatter layer 1: pure ld/fmul/red -------------------------
// 64 threads per edge: each handles one float4 of the 256-wide feature
__global__ void __launch_bounds__(256)
scatter1_kernel(const int* __restrict__ ei, int E, int N) {
    long long idx = (long long)blockIdx.x * blockDim.x + threadIdx.x;
    int ET = E + N;
    int e = (int)(idx >> 6);
    if (e >= ET) return;
    int t = (int)(idx & 63);     // float4 index; head = t>>3
    int h = t >> 3;
    int src, dst;
    if (e < E) { src = ei[e]; dst = ei[E + e]; } else { src = dst = e - E; }
    float alpha = g_w1[(size_t)e * HEADS + h] * g_den1[dst * HEADS + h];
    float4 hv = *reinterpret_cast<const float4*>(g_h1 + (size_t)src * F1 + t * 4);
    red_add_v4(g_agg1 + (size_t)dst * F1 + t * 4,
               make_float4(alpha * hv.x, alpha * hv.y, alpha * hv.z, alpha * hv.w));
}

// ---------------- ELU(agg1 + b1) in place ----------------------------------
__global__ void elu_kernel(const float* __restrict__ b1) {
    int i = blockIdx.x * blockDim.x + threadIdx.x;
    if (i >= NN * F1) return;
    float v = g_agg1[i] + b1[i & (F1 - 1)];
    g_agg1[i] = v > 0.f ? v : expm1f(v);
}

// ---------------- GEMM2 + scores2 (warp per node) --------------------------
__global__ void __launch_bounds__(256)
gemm2_kernel(const float* __restrict__ W2, const float* __restrict__ asrc,
             const float* __restrict__ adst) {
    int w = (blockIdx.x * blockDim.x + threadIdx.x) >> 5;
    int lane = threadIdx.x & 31;
    if (w >= NN) return;
    const float* row = g_agg1 + (size_t)w * F1;
    float rv[8];
#pragma unroll
    for (int j = 0; j < 8; j++) rv[j] = row[lane + j * 32];
    float acc = 0.f;
#pragma unroll
    for (int j = 0; j < 8; j++) {
#pragma unroll
        for (int s = 0; s < 32; s++) {
            float a = __shfl_sync(0xffffffffu, rv[j], s);
            acc += a * __ldg(&W2[(j * 32 + s) * NCLASS + lane]);
        }
    }
    g_h2[(size_t)w * NCLASS + lane] = acc;
    float ps = warp_sum(acc * asrc[lane]);
    float pd = warp_sum(acc * adst[lane]);
    if (lane == 0) { g_ssrc2[w] = ps; g_sdst2[w] = pd; }
}

// ---------------- edge pass layer 2 -----------------------------------------
__global__ void __launch_bounds__(256)
esum2_kernel(const int* __restrict__ ei, int E, int N) {
    int e = blockIdx.x * blockDim.x + threadIdx.x;
    if (e >= E + N) return;
    int src, dst;
    if (e < E) { src = ei[e]; dst = ei[E + e]; } else { src = dst = e - E; }
    float w = __expf(lrelu(g_ssrc2[src] + g_sdst2[dst]));
    g_w2[e] = w;
    atomicAdd(&g_den2[dst], w);
}

__global__ void invden2_kernel() {
    int i = blockIdx.x * blockDim.x + threadIdx.x;
    if (i < NN) g_den2[i] = __frcp_rn(g_den2[i] + 1e-16f);
}

// 8 threads per edge (8 x float4 = 32 floats)
__global__ void __launch_bounds__(256)
scatter2_kernel(const int* __restrict__ ei, int E, int N,
                float* __restrict__ out) {
    long long idx = (long long)blockIdx.x * blockDim.x + threadIdx.x;
    int e = (int)(idx >> 3);
    if (e >= E + N) return;
    int t = (int)(idx & 7);
    int src, dst;
    if (e < E) { src = ei[e]; dst = ei[E + e]; } else { src = dst = e - E; }
    float alpha = g_w2[e] * g_den2[dst];
    float4 hv = *reinterpret_cast<const float4*>(g_h2 + (size_t)src * NCLASS + t * 4);
    red_add_v4(out + (size_t)dst * NCLASS + t * 4,
               make_float4(alpha * hv.x, alpha * hv.y, alpha * hv.z, alpha * hv.w));
}

// ---------------- epilogue: out += b2 + 1e-6 --------------------------------
__global__ void epi_kernel(float* __restrict__ out, const float* __restrict__ b2) {
    int i = blockIdx.x * blockDim.x + threadIdx.x;
    if (i >= NN * NCLASS) return;
    out[i] = out[i] + b2[i & (NCLASS - 1)] + 1e-6f;
}

// ---------------- launch ----------------------------------------------------
extern "C" void kernel_launch(void* const* d_in, const int* in_sizes, int n_in,
                              void* d_out, int out_size) {
    const float* x     = (const float*)d_in[0];
    const int*   ei    = (const int*)d_in[1];     // int32 [2, E]
    const float* W1    = (const float*)d_in[2];
    const float* asrc1 = (const float*)d_in[3];
    const float* adst1 = (const float*)d_in[4];
    const float* b1    = (const float*)d_in[5];
    const float* W2    = (const float*)d_in[6];
    const float* asrc2 = (const float*)d_in[7];
    const float* adst2 = (const float*)d_in[8];
    const float* b2    = (const float*)d_in[9];
    float* out = (float*)d_out;

    int N  = in_sizes[0] / F_IN;   // 50000
    int E  = in_sizes[1] / 2;      // 800000
    int ET = E + N;

    init_kernel<<<(N * F1 + 255) / 256, 256>>>(out, out_size);

    gemm1_kernel<<<dim3(F1 / 64, (N + 127) / 128), 256>>>(x, W1);
    scores1_kernel<<<N, 256>>>(asrc1, adst1);

    esum1_kernel<<<(unsigned)(((long long)ET * 8 + 255) / 256), 256>>>(ei, E, N);
    invden1_kernel<<<(N * HEADS + 255) / 256, 256>>>();
    scatter1_kernel<<<(unsigned)(((long long)ET * 64 + 255) / 256), 256>>>(ei, E, N);

    elu_kernel<<<(N * F1 + 255) / 256, 256>>>(b1);

    gemm2_kernel<<<(N * 32 + 255) / 256, 256>>>(W2, asrc2, adst2);

    esum2_kernel<<<(ET + 255) / 256, 256>>>(ei, E, N);
    invden2_kernel<<<(N + 255) / 256, 256>>>();
    scatter2_kernel<<<(unsigned)(((long long)ET * 8 + 255) / 256), 256>>>(ei, E, N, out);

    epi_kernel<<<(N * NCLASS + 255) / 256, 256>>>(out, b2);
}

// round 4
// speedup vs baseline: 1.5818x; 1.1319x over previous
#include <cuda_runtime.h>
#include <cuda_bf16.h>
#include <math.h>

// Problem shapes (fixed by the dataset)
#define NN      50000      // nodes
#define F_IN    512
#define F1      256        // HEADS*HID
#define HEADS   8
#define HID     32
#define NCLASS  32
#define NEG_SLOPE 0.2f
#define ET_MAX  (800000 + NN)

// ---------------- scratch (device globals; no allocation allowed) ----------
__device__ float g_h1  [(size_t)NN * F1];     // x @ W1            [N,256]
__device__ float g_agg1[(size_t)NN * F1];     // ELU(layer-1 aggregate)
__device__ float g_h2  [(size_t)NN * NCLASS];
__device__ float g_w1  [(size_t)HEADS * ET_MAX];  // per-edge exp, [H][ET]
__device__ float g_w2  [(size_t)ET_MAX];
__device__ float g_ssrc1[NN * HEADS];
__device__ float g_sdst1[NN * HEADS];
__device__ float g_ssrc2[NN];
__device__ float g_sdst2[NN];
// CSR
__device__ int g_deg   [NN];
__device__ int g_rowptr[NN + 1];
__device__ int g_cursor[NN];
__device__ int g_esrc  [ET_MAX];

// ---------------- helpers ---------------------------------------------------
__device__ __forceinline__ float warp_sum(float v) {
#pragma unroll
    for (int o = 16; o > 0; o >>= 1) v += __shfl_down_sync(0xffffffffu, v, o);
    return v;
}
__device__ __forceinline__ float warp_allsum(float v) {
#pragma unroll
    for (int o = 16; o > 0; o >>= 1) v += __shfl_xor_sync(0xffffffffu, v, o);
    return v;
}
__device__ __forceinline__ float lrelu(float s) {
    return s > 0.f ? s : NEG_SLOPE * s;
}
__device__ __forceinline__ unsigned f2tf32(float f) {
    unsigned u;
    asm("cvt.rna.tf32.f32 %0, %1;" : "=r"(u) : "f"(f));
    return u;
}
__device__ __forceinline__ void mma_tf32(float* d, const unsigned* a, const unsigned* b) {
    asm volatile(
        "mma.sync.aligned.m16n8k8.row.col.f32.tf32.tf32.f32 "
        "{%0,%1,%2,%3}, {%4,%5,%6,%7}, {%8,%9}, {%0,%1,%2,%3};"
        : "+f"(d[0]), "+f"(d[1]), "+f"(d[2]), "+f"(d[3])
        : "r"(a[0]), "r"(a[1]), "r"(a[2]), "r"(a[3]), "r"(b[0]), "r"(b[1]));
}
__device__ __forceinline__ void cp_async16(void* smem, const void* gmem, int bytes) {
    unsigned s = (unsigned)__cvta_generic_to_shared(smem);
    asm volatile("cp.async.ca.shared.global [%0], [%1], 16, %2;"
                 :: "r"(s), "l"(gmem), "r"(bytes) : "memory");
}
#define CP_COMMIT() asm volatile("cp.async.commit_group;" ::: "memory")
#define CP_WAIT(n)  asm volatile("cp.async.wait_group %0;" :: "n"(n) : "memory")

// ---------------- CSR build --------------------------------------------------
__global__ void deg_init_kernel() {
    int i = blockIdx.x * blockDim.x + threadIdx.x;
    if (i < NN) { g_deg[i] = 1; g_cursor[i] = 0; }   // self loop counts
}
__global__ void deg_count_kernel(const int* __restrict__ ei, int E) {
    int e = blockIdx.x * blockDim.x + threadIdx.x;
    if (e < E) atomicAdd(&g_deg[ei[E + e]], 1);
}
__global__ void scan_kernel(int N) {
    __shared__ int bs[1024];
    int t = threadIdx.x;
    const int CH = (NN + 1023) / 1024;   // 49
    int lo = t * CH, hi = min(lo + CH, N);
    int s = 0;
    for (int i = lo; i < hi; i++) s += g_deg[i];
    int v = s;
    bs[t] = v; __syncthreads();
    for (int off = 1; off < 1024; off <<= 1) {
        int u = (t >= off) ? bs[t - off] : 0;
        __syncthreads();
        v += u; bs[t] = v;
        __syncthreads();
    }
    int run = v - s;                      // exclusive prefix
    for (int i = lo; i < hi; i++) { g_rowptr[i] = run; run += g_deg[i]; }
    if (t == 1023) g_rowptr[N] = bs[1023];
}
__global__ void fill_kernel(const int* __restrict__ ei, int E, int N) {
    int idx = blockIdx.x * blockDim.x + threadIdx.x;
    int ET = E + N;
    if (idx >= ET) return;
    int src, dst;
    if (idx < E) { src = ei[idx]; dst = ei[E + idx]; } else { src = dst = idx - E; }
    int pos = g_rowptr[dst] + atomicAdd(&g_cursor[dst], 1);
    g_esrc[pos] = src;
}

// ---------------- GEMM1 (tf32 mma, cp.async 2-stage): g_h1 = x @ W1 ---------
// Block tile 128(M) x 64(N) x 16(K). 8 warps: 4(M) x 2(N), warp tile 32x32.
__global__ void __launch_bounds__(256)
gemm1_kernel(const float* __restrict__ A, const float* __restrict__ B) {
    __shared__ float As[2][128][20];   // 16 data + 4 pad (80B rows, 16B aligned)
    __shared__ float Bs[2][16][72];    // 64 data + 8 pad

    const int M = NN, K = F_IN;
    int tid  = threadIdx.x;
    int lane = tid & 31, wid = tid >> 5;
    int warp_m = wid >> 1, warp_n = wid & 1;
    int row0 = blockIdx.y * 128, col0 = blockIdx.x * 64;

    int g  = lane >> 2;   // 0..7
    int tg = lane & 3;    // 0..3

    float acc[2][4][4];
#pragma unroll
    for (int i = 0; i < 2; i++)
#pragma unroll
        for (int j = 0; j < 4; j++)
#pragma unroll
            for (int r = 0; r < 4; r++) acc[i][j][r] = 0.f;

    // async-load assignments
    int a_r = tid >> 1, a_c = (tid & 1) * 8;   // 2x 16B per thread for A
    int b_r = tid >> 4, b_c = (tid & 15) * 4;  // 1x 16B per thread for B
    int gr = row0 + a_r;
    const float* a_base = A + (size_t)min(gr, M - 1) * K + a_c;
    int a_bytes = (gr < M) ? 16 : 0;
    const float* b_base = B + (size_t)b_r * F1 + col0 + b_c;

    // prologue: stage 0
    cp_async16(&As[0][a_r][a_c],     a_base,     a_bytes);
    cp_async16(&As[0][a_r][a_c + 4], a_base + 4, a_bytes);
    cp_async16(&Bs[0][b_r][b_c],     b_base,     16);
    CP_COMMIT();

    const int NT = K / 16;   // 32
    for (int kt = 0; kt < NT; kt++) {
        int buf = kt & 1;
        if (kt + 1 < NT) {
            int k1 = (kt + 1) * 16;
            cp_async16(&As[buf ^ 1][a_r][a_c],     a_base + k1,     a_bytes);
            cp_async16(&As[buf ^ 1][a_r][a_c + 4], a_base + k1 + 4, a_bytes);
            cp_async16(&Bs[buf ^ 1][b_r][b_c],     b_base + (size_t)k1 * F1, 16);
            CP_COMMIT();
            CP_WAIT(1);
        } else {
            CP_WAIT(0);
        }
        __syncthreads();

#pragma unroll
        for (int ks = 0; ks < 2; ks++) {
            int kb = ks * 8;
            unsigned afr[2][4];
#pragma unroll
            for (int mt = 0; mt < 2; mt++) {
                int rb = warp_m * 32 + mt * 16;
                afr[mt][0] = f2tf32(As[buf][rb + g    ][kb + tg    ]);
                afr[mt][1] = f2tf32(As[buf][rb + g + 8][kb + tg    ]);
                afr[mt][2] = f2tf32(As[buf][rb + g    ][kb + tg + 4]);
                afr[mt][3] = f2tf32(As[buf][rb + g + 8][kb + tg + 4]);
            }
            unsigned bfr[4][2];
#pragma unroll
            for (int nt = 0; nt < 4; nt++) {
                int nb = warp_n * 32 + nt * 8;
                bfr[nt][0] = f2tf32(Bs[buf][kb + tg    ][nb + g]);
                bfr[nt][1] = f2tf32(Bs[buf][kb + tg + 4][nb + g]);
            }
#pragma unroll
            for (int mt = 0; mt < 2; mt++)
#pragma unroll
                for (int nt = 0; nt < 4; nt++)
                    mma_tf32(acc[mt][nt], afr[mt], bfr[nt]);
        }
        __syncthreads();
    }

    // store accumulators
#pragma unroll
    for (int mt = 0; mt < 2; mt++) {
#pragma unroll
        for (int half = 0; half < 2; half++) {
            int grr = row0 + warp_m * 32 + mt * 16 + g + half * 8;
            if (grr >= M) continue;
#pragma unroll
            for (int nt = 0; nt < 4; nt++) {
                int gc = col0 + warp_n * 32 + nt * 8 + 2 * tg;
                float2 v = make_float2(acc[mt][nt][half * 2], acc[mt][nt][half * 2 + 1]);
                *reinterpret_cast<float2*>(&g_h1[(size_t)grr * F1 + gc]) = v;
            }
        }
    }
}

// ---------------- per-node attention scores layer 1 -------------------------
__global__ void __launch_bounds__(256)
scores1_kernel(const float* __restrict__ asrc, const float* __restrict__ adst) {
    int n = blockIdx.x, t = threadIdx.x;      // t = head*32 + c
    float v = g_h1[(size_t)n * F1 + t];
    float ps = warp_sum(v * asrc[t]);
    float pd = warp_sum(v * adst[t]);
    if ((t & 31) == 0) {
        int h = t >> 5;
        g_ssrc1[n * HEADS + h] = ps;
        g_sdst1[n * HEADS + h] = pd;
    }
}

// ---------------- layer-1 fused softmax + aggregate + ELU(+b1) --------------
// block = node, warp = head, lane = feature within head
__global__ void __launch_bounds__(256)
agg1_kernel(const float* __restrict__ b1) {
    int n = blockIdx.x;
    int wid = threadIdx.x >> 5, lane = threadIdx.x & 31;
    int h = wid;
    int r0 = g_rowptr[n], r1 = g_rowptr[n + 1];

    float sdst = g_sdst1[n * HEADS + h];
    float* w1h = g_w1 + (size_t)h * ET_MAX;

    // phase 1: per-edge exp, warp-local denominator (no atomics)
    float den = 0.f;
    for (int p = r0 + lane; p < r1; p += 32) {
        int src = g_esrc[p];
        float w = __expf(lrelu(g_ssrc1[src * HEADS + h] + sdst));
        w1h[p] = w;
        den += w;
    }
    den = warp_allsum(den);
    float inv = __frcp_rn(den + 1e-16f);
    __threadfence_block();
    __syncwarp();

    // phase 2: register-accumulated gather with depth-4 src prefetch
    int d = r1 - r0;
    int s[4];
#pragma unroll
    for (int i = 0; i < 4; i++) s[i] = (r0 + i < r1) ? g_esrc[r0 + i] : 0;
    float acc = 0.f;
#pragma unroll 4
    for (int i = 0; i < d; i++) {
        int src = s[i & 3];
        float a = w1h[r0 + i] * inv;
        float hv = g_h1[(size_t)src * F1 + h * 32 + lane];
        if (r0 + i + 4 < r1) s[i & 3] = g_esrc[r0 + i + 4];
        acc = fmaf(a, hv, acc);
    }
    float v = acc + b1[h * 32 + lane];
    g_agg1[(size_t)n * F1 + h * 32 + lane] = v > 0.f ? v : expm1f(v);
}

// ---------------- GEMM2 + scores2 (warp per node) --------------------------
__global__ void __launch_bounds__(256)
gemm2_kernel(const float* __restrict__ W2, const float* __restrict__ asrc,
             const float* __restrict__ adst) {
    int w = (blockIdx.x * blockDim.x + threadIdx.x) >> 5;
    int lane = threadIdx.x & 31;
    if (w >= NN) return;
    const float* row = g_agg1 + (size_t)w * F1;
    float rv[8];
#pragma unroll
    for (int j = 0; j < 8; j++) rv[j] = row[lane + j * 32];
    float acc = 0.f;
#pragma unroll
    for (int j = 0; j < 8; j++) {
#pragma unroll
        for (int s = 0; s < 32; s++) {
            float a = __shfl_sync(0xffffffffu, rv[j], s);
            acc += a * __ldg(&W2[(j * 32 + s) * NCLASS + lane]);
        }
    }
    g_h2[(size_t)w * NCLASS + lane] = acc;
    float ps = warp_sum(acc * asrc[lane]);
    float pd = warp_sum(acc * adst[lane]);
    if (lane == 0) { g_ssrc2[w] = ps; g_sdst2[w] = pd; }
}

// ---------------- layer-2 fused softmax + aggregate (+b2 + 1e-6) ------------
// warp per node (NCLASS = 32), 8 nodes per block
__global__ void __launch_bounds__(256)
agg2_kernel(const float* __restrict__ b2, float* __restrict__ out) {
    int wid = threadIdx.x >> 5, lane = threadIdx.x & 31;
    int n = blockIdx.x * 8 + wid;
    if (n >= NN) return;
    int r0 = g_rowptr[n], r1 = g_rowptr[n + 1];
    float sdst = g_sdst2[n];

    float den = 0.f;
    for (int p = r0 + lane; p < r1; p += 32) {
        int src = g_esrc[p];
        float w = __expf(lrelu(g_ssrc2[src] + sdst));
        g_w2[p] = w;
        den += w;
    }
    den = warp_allsum(den);
    float inv = __frcp_rn(den + 1e-16f);
    __threadfence_block();
    __syncwarp();

    int d = r1 - r0;
    int s[4];
#pragma unroll
    for (int i = 0; i < 4; i++) s[i] = (r0 + i < r1) ? g_esrc[r0 + i] : 0;
    float acc = 0.f;
#pragma unroll 4
    for (int i = 0; i < d; i++) {
        int src = s[i & 3];
        float a = g_w2[r0 + i] * inv;
        float hv = g_h2[(size_t)src * NCLASS + lane];
        if (r0 + i + 4 < r1) s[i & 3] = g_esrc[r0 + i + 4];
        acc = fmaf(a, hv, acc);
    }
    out[(size_t)n * NCLASS + lane] = acc + b2[lane] + 1e-6f;
}

// ---------------- launch ----------------------------------------------------
extern "C" void kernel_launch(void* const* d_in, const int* in_sizes, int n_in,
                              void* d_out, int out_size) {
    const float* x     = (const float*)d_in[0];
    const int*   ei    = (const int*)d_in[1];     // int32 [2, E]
    const float* W1    = (const float*)d_in[2];
    const float* asrc1 = (const float*)d_in[3];
    const float* adst1 = (const float*)d_in[4];
    const float* b1    = (const float*)d_in[5];
    const float* W2    = (const float*)d_in[6];
    const float* asrc2 = (const float*)d_in[7];
    const float* adst2 = (const float*)d_in[8];
    const float* b2    = (const float*)d_in[9];
    float* out = (float*)d_out;

    int N  = in_sizes[0] / F_IN;   // 50000
    int E  = in_sizes[1] / 2;      // 800000
    int ET = E + N;

    // CSR build (runs concurrently-independent of gemm1 in issue order)
    deg_init_kernel<<<(N + 255) / 256, 256>>>();
    deg_count_kernel<<<(E + 255) / 256, 256>>>(ei, E);
    scan_kernel<<<1, 1024>>>(N);
    fill_kernel<<<(ET + 255) / 256, 256>>>(ei, E, N);

    gemm1_kernel<<<dim3(F1 / 64, (N + 127) / 128), 256>>>(x, W1);
    scores1_kernel<<<N, 256>>>(asrc1, adst1);

    agg1_kernel<<<N, 256>>>(b1);

    gemm2_kernel<<<(N * 32 + 255) / 256, 256>>>(W2, asrc2, adst2);

    agg2_kernel<<<(N + 7) / 8, 256>>>(b2, out);
}

// round 5
// speedup vs baseline: 2.4717x; 1.5626x over previous
#include <cuda_runtime.h>
#include <cuda_bf16.h>
#include <math.h>

#define NN      50000
#define F_IN    512
#define F1      256
#define HEADS   8
#define HID     32
#define NCLASS  32
#define NEG_SLOPE 0.2f
#define ET_MAX  (800000 + NN)
#define CAP     128
#define SCAN_B  ((NN + 255) / 256)

// ---------------- scratch ----------------------------------------------------
__device__ float g_h1  [(size_t)NN * F1];
__device__ float g_agg1[(size_t)NN * F1];
__device__ float g_h2  [(size_t)NN * NCLASS];
__device__ float g_w1  [(size_t)HEADS * ET_MAX];  // fallback only
__device__ float g_w2  [(size_t)ET_MAX];          // fallback only
__device__ float g_ssrc1[NN * HEADS];
__device__ float g_sdst1[NN * HEADS];
__device__ float g_ssrc2[NN];
__device__ float g_sdst2[NN];
__device__ int g_deg   [NN];
__device__ int g_rowptr[NN + 1];
__device__ int g_cursor[NN];
__device__ int g_esrc  [ET_MAX];
__device__ int g_bsum  [256];
__device__ int g_boff  [256];

// ---------------- helpers ----------------------------------------------------
__device__ __forceinline__ float warp_allsum(float v) {
#pragma unroll
    for (int o = 16; o > 0; o >>= 1) v += __shfl_xor_sync(0xffffffffu, v, o);
    return v;
}
__device__ __forceinline__ float lrelu(float s) {
    return s > 0.f ? s : NEG_SLOPE * s;
}
__device__ __forceinline__ unsigned f2tf32(float f) {
    unsigned u;
    asm("cvt.rna.tf32.f32 %0, %1;" : "=r"(u) : "f"(f));
    return u;
}
__device__ __forceinline__ void mma_tf32(float* d, const unsigned* a, const unsigned* b) {
    asm volatile(
        "mma.sync.aligned.m16n8k8.row.col.f32.tf32.tf32.f32 "
        "{%0,%1,%2,%3}, {%4,%5,%6,%7}, {%8,%9}, {%0,%1,%2,%3};"
        : "+f"(d[0]), "+f"(d[1]), "+f"(d[2]), "+f"(d[3])
        : "r"(a[0]), "r"(a[1]), "r"(a[2]), "r"(a[3]), "r"(b[0]), "r"(b[1]));
}
__device__ __forceinline__ void cp_async16(void* smem, const void* gmem, int bytes) {
    unsigned s = (unsigned)__cvta_generic_to_shared(smem);
    asm volatile("cp.async.ca.shared.global [%0], [%1], 16, %2;"
                 :: "r"(s), "l"(gmem), "r"(bytes) : "memory");
}
#define CP_COMMIT() asm volatile("cp.async.commit_group;" ::: "memory")
#define CP_WAIT(n)  asm volatile("cp.async.wait_group %0;" :: "n"(n) : "memory")

// ---------------- CSR build --------------------------------------------------
__global__ void deg_init_kernel() {
    int i = blockIdx.x * blockDim.x + threadIdx.x;
    if (i < NN) { g_deg[i] = 1; g_cursor[i] = 0; }
}
__global__ void deg_count_kernel(const int* __restrict__ ei, int E) {
    int e = blockIdx.x * blockDim.x + threadIdx.x;
    if (e < E) atomicAdd(&g_deg[ei[E + e]], 1);
}
__global__ void scan_p1() {
    __shared__ int sh[256];
    int b = blockIdx.x, t = threadIdx.x;
    int i = b * 256 + t;
    int d = (i < NN) ? g_deg[i] : 0;
    int v = d;
    sh[t] = v; __syncthreads();
#pragma unroll
    for (int off = 1; off < 256; off <<= 1) {
        int u = (t >= off) ? sh[t - off] : 0;
        __syncthreads();
        v += u; sh[t] = v;
        __syncthreads();
    }
    if (i < NN) g_rowptr[i] = v;      // block-local inclusive
    if (t == 255) g_bsum[b] = v;
}
__global__ void scan_p2(int nb) {
    __shared__ int sh[256];
    int t = threadIdx.x;
    int d = (t < nb) ? g_bsum[t] : 0;
    int v = d;
    sh[t] = v; __syncthreads();
#pragma unroll
    for (int off = 1; off < 256; off <<= 1) {
        int u = (t >= off) ? sh[t - off] : 0;
        __syncthreads();
        v += u; sh[t] = v;
        __syncthreads();
    }
    g_boff[t] = v - d;                // exclusive
}
__global__ void scan_p3(int N) {
    int i = blockIdx.x * 256 + threadIdx.x;
    if (i < N) {
        int incl = g_rowptr[i] + g_boff[blockIdx.x];
        g_rowptr[i] = incl - g_deg[i];
        if (i == N - 1) g_rowptr[N] = incl;
    }
}
__global__ void fill_kernel(const int* __restrict__ ei, int E, int N) {
    int idx = blockIdx.x * blockDim.x + threadIdx.x;
    int ET = E + N;
    if (idx >= ET) return;
    int src, dst;
    if (idx < E) { src = ei[idx]; dst = ei[E + idx]; } else { src = dst = idx - E; }
    int pos = g_rowptr[dst] + atomicAdd(&g_cursor[dst], 1);
    g_esrc[pos] = src;
}

// ---------------- GEMM1 (tf32, 128x128x16, 2-stage) + fused scores1 ---------
// 8 warps: warp_m = wid>>2 (2), warp_n = wid&3 (4). Warp tile 64x32.
__global__ void __launch_bounds__(256)
gemm1_kernel(const float* __restrict__ A, const float* __restrict__ B,
             const float* __restrict__ asrc, const float* __restrict__ adst) {
    __shared__ float As[2][128][20];
    __shared__ float Bs[2][16][132];

    const int M = NN, K = F_IN;
    int tid  = threadIdx.x;
    int lane = tid & 31, wid = tid >> 5;
    int warp_m = wid >> 2, warp_n = wid & 3;
    int row0 = blockIdx.y * 128, col0 = blockIdx.x * 128;

    int g  = lane >> 2;
    int tg = lane & 3;

    float acc[4][4][4];
#pragma unroll
    for (int i = 0; i < 4; i++)
#pragma unroll
        for (int j = 0; j < 4; j++)
#pragma unroll
            for (int r = 0; r < 4; r++) acc[i][j][r] = 0.f;

    int a_r = tid >> 1, a_c = (tid & 1) * 8;
    int b_r = tid >> 4, b_c = (tid & 15) * 8;
    int gr = row0 + a_r;
    const float* a_base = A + (size_t)min(gr, M - 1) * K + a_c;
    int a_bytes = (gr < M) ? 16 : 0;
    const float* b_base = B + (size_t)b_r * F1 + col0 + b_c;

    cp_async16(&As[0][a_r][a_c],     a_base,     a_bytes);
    cp_async16(&As[0][a_r][a_c + 4], a_base + 4, a_bytes);
    cp_async16(&Bs[0][b_r][b_c],     b_base,     16);
    cp_async16(&Bs[0][b_r][b_c + 4], b_base + 4, 16);
    CP_COMMIT();

    const int NT = K / 16;
    for (int kt = 0; kt < NT; kt++) {
        int buf = kt & 1;
        if (kt + 1 < NT) {
            int k1 = (kt + 1) * 16;
            cp_async16(&As[buf ^ 1][a_r][a_c],     a_base + k1,     a_bytes);
            cp_async16(&As[buf ^ 1][a_r][a_c + 4], a_base + k1 + 4, a_bytes);
            cp_async16(&Bs[buf ^ 1][b_r][b_c],     b_base + (size_t)k1 * F1,     16);
            cp_async16(&Bs[buf ^ 1][b_r][b_c + 4], b_base + (size_t)k1 * F1 + 4, 16);
            CP_COMMIT();
            CP_WAIT(1);
        } else {
            CP_WAIT(0);
        }
        __syncthreads();

#pragma unroll
        for (int ks = 0; ks < 2; ks++) {
            int kb = ks * 8;
            unsigned bfr[4][2];
#pragma unroll
            for (int nt = 0; nt < 4; nt++) {
                int nb = warp_n * 32 + nt * 8;
                bfr[nt][0] = f2tf32(Bs[buf][kb + tg    ][nb + g]);
                bfr[nt][1] = f2tf32(Bs[buf][kb + tg + 4][nb + g]);
            }
#pragma unroll
            for (int mt = 0; mt < 4; mt++) {
                int rb = warp_m * 64 + mt * 16;
                unsigned afr[4];
                afr[0] = f2tf32(As[buf][rb + g    ][kb + tg    ]);
                afr[1] = f2tf32(As[buf][rb + g + 8][kb + tg    ]);
                afr[2] = f2tf32(As[buf][rb + g    ][kb + tg + 4]);
                afr[3] = f2tf32(As[buf][rb + g + 8][kb + tg + 4]);
#pragma unroll
                for (int nt = 0; nt < 4; nt++)
                    mma_tf32(acc[mt][nt], afr, bfr[nt]);
            }
        }
        __syncthreads();
    }

    // store h1
#pragma unroll
    for (int mt = 0; mt < 4; mt++) {
#pragma unroll
        for (int half = 0; half < 2; half++) {
            int grr = row0 + warp_m * 64 + mt * 16 + g + half * 8;
            if (grr >= M) continue;
#pragma unroll
            for (int nt = 0; nt < 4; nt++) {
                int gc = col0 + warp_n * 32 + nt * 8 + 2 * tg;
                float2 v = make_float2(acc[mt][nt][half * 2], acc[mt][nt][half * 2 + 1]);
                *reinterpret_cast<float2*>(&g_h1[(size_t)grr * F1 + gc]) = v;
            }
        }
    }

    // fused scores: this warp's 32 cols = one head
    int head = blockIdx.x * 4 + warp_n;
    float as_[4][2], ad_[4][2];
#pragma unroll
    for (int nt = 0; nt < 4; nt++) {
        int cc = nt * 8 + 2 * tg;
        as_[nt][0] = asrc[head * HID + cc];     as_[nt][1] = asrc[head * HID + cc + 1];
        ad_[nt][0] = adst[head * HID + cc];     ad_[nt][1] = adst[head * HID + cc + 1];
    }
#pragma unroll
    for (int mt = 0; mt < 4; mt++) {
#pragma unroll
        for (int half = 0; half < 2; half++) {
            float ps = 0.f, pd = 0.f;
#pragma unroll
            for (int nt = 0; nt < 4; nt++) {
                ps += acc[mt][nt][2*half] * as_[nt][0] + acc[mt][nt][2*half+1] * as_[nt][1];
                pd += acc[mt][nt][2*half] * ad_[nt][0] + acc[mt][nt][2*half+1] * ad_[nt][1];
            }
            ps += __shfl_xor_sync(0xffffffffu, ps, 1);
            ps += __shfl_xor_sync(0xffffffffu, ps, 2);
            pd += __shfl_xor_sync(0xffffffffu, pd, 1);
            pd += __shfl_xor_sync(0xffffffffu, pd, 2);
            int row = row0 + warp_m * 64 + mt * 16 + g + half * 8;
            if (row < M && tg == 0) {
                g_ssrc1[row * HEADS + head] = ps;
                g_sdst1[row * HEADS + head] = pd;
            }
        }
    }
}

// ---------------- layer-1 fused softmax + aggregate + ELU(+b1) --------------
__global__ void __launch_bounds__(256)
agg1_kernel(const float* __restrict__ b1) {
    __shared__ int   s_src[CAP];
    __shared__ float s_w[HEADS][CAP];
    int n = blockIdx.x;
    int tid = threadIdx.x, h = tid >> 5, lane = tid & 31;
    int r0 = g_rowptr[n], r1 = g_rowptr[n + 1], d = r1 - r0;
    float sdst = g_sdst1[n * HEADS + h];

    if (d <= CAP) {
        for (int p = tid; p < d; p += 256) s_src[p] = g_esrc[r0 + p];
        __syncthreads();
        float den = 0.f;
        for (int i = lane; i < d; i += 32) {
            int src = s_src[i];
            float w = __expf(lrelu(g_ssrc1[src * HEADS + h] + sdst));
            s_w[h][i] = w;
            den += w;
        }
        den = warp_allsum(den);
        float inv = __frcp_rn(den + 1e-16f);
        __syncwarp();
        float acc = 0.f;
#pragma unroll 4
        for (int i = 0; i < d; i++) {
            float a = s_w[h][i];
            int src = s_src[i];
            acc = fmaf(a, g_h1[(size_t)src * F1 + h * HID + lane], acc);
        }
        acc *= inv;
        float v = acc + b1[h * HID + lane];
        g_agg1[(size_t)n * F1 + h * HID + lane] = v > 0.f ? v : expm1f(v);
    } else {
        // fallback (degree > CAP): global w buffer
        float* w1h = g_w1 + (size_t)h * ET_MAX;
        float den = 0.f;
        for (int p = r0 + lane; p < r1; p += 32) {
            int src = g_esrc[p];
            float w = __expf(lrelu(g_ssrc1[src * HEADS + h] + sdst));
            w1h[p] = w; den += w;
        }
        den = warp_allsum(den);
        float inv = __frcp_rn(den + 1e-16f);
        __threadfence_block();
        __syncwarp();
        float acc = 0.f;
        for (int p = r0; p < r1; p++) {
            int src = g_esrc[p];
            acc = fmaf(w1h[p], g_h1[(size_t)src * F1 + h * HID + lane], acc);
        }
        acc *= inv;
        float v = acc + b1[h * HID + lane];
        g_agg1[(size_t)n * F1 + h * HID + lane] = v > 0.f ? v : expm1f(v);
    }
}

// ---------------- GEMM2 (tf32, 128x32x16) + fused scores2 -------------------
// 8 warps, warp tile 16x32 (warp_m = wid).
__global__ void __launch_bounds__(256)
gemm2_kernel(const float* __restrict__ W2, const float* __restrict__ asrc,
             const float* __restrict__ adst) {
    __shared__ float As[2][128][20];
    __shared__ float Bs[2][16][36];

    const int M = NN, K = F1;
    int tid  = threadIdx.x;
    int lane = tid & 31, wid = tid >> 5;
    int row0 = blockIdx.x * 128;
    int g = lane >> 2, tg = lane & 3;

    float acc[4][4];
#pragma unroll
    for (int j = 0; j < 4; j++)
#pragma unroll
        for (int r = 0; r < 4; r++) acc[j][r] = 0.f;

    int a_r = tid >> 1, a_c = (tid & 1) * 8;
    int gr = row0 + a_r;
    const float* a_base = g_agg1 + (size_t)min(gr, M - 1) * K + a_c;
    int a_bytes = (gr < M) ? 16 : 0;
    int b_r = tid >> 3, b_c = (tid & 7) * 4;     // only tid<128 loads B
    const float* b_base = W2 + (size_t)b_r * NCLASS + b_c;

    cp_async16(&As[0][a_r][a_c],     a_base,     a_bytes);
    cp_async16(&As[0][a_r][a_c + 4], a_base + 4, a_bytes);
    if (tid < 128) cp_async16(&Bs[0][b_r][b_c], b_base, 16);
    CP_COMMIT();

    const int NT = K / 16;   // 16
    for (int kt = 0; kt < NT; kt++) {
        int buf = kt & 1;
        if (kt + 1 < NT) {
            int k1 = (kt + 1) * 16;
            cp_async16(&As[buf ^ 1][a_r][a_c],     a_base + k1,     a_bytes);
            cp_async16(&As[buf ^ 1][a_r][a_c + 4], a_base + k1 + 4, a_bytes);
            if (tid < 128) cp_async16(&Bs[buf ^ 1][b_r][b_c],
                                      b_base + (size_t)k1 * NCLASS, 16);
            CP_COMMIT();
            CP_WAIT(1);
        } else {
            CP_WAIT(0);
        }
        __syncthreads();

#pragma unroll
        for (int ks = 0; ks < 2; ks++) {
            int kb = ks * 8;
            int rb = wid * 16;
            unsigned afr[4];
            afr[0] = f2tf32(As[buf][rb + g    ][kb + tg    ]);
            afr[1] = f2tf32(As[buf][rb + g + 8][kb + tg    ]);
            afr[2] = f2tf32(As[buf][rb + g    ][kb + tg + 4]);
            afr[3] = f2tf32(As[buf][rb + g + 8][kb + tg + 4]);
#pragma unroll
            for (int nt = 0; nt < 4; nt++) {
                int nb = nt * 8;
                unsigned bfr[2];
                bfr[0] = f2tf32(Bs[buf][kb + tg    ][nb + g]);
                bfr[1] = f2tf32(Bs[buf][kb + tg + 4][nb + g]);
                mma_tf32(acc[nt], afr, bfr);
            }
        }
        __syncthreads();
    }

    // store h2 + fused scores2
    float as_[4][2], ad_[4][2];
#pragma unroll
    for (int nt = 0; nt < 4; nt++) {
        int cc = nt * 8 + 2 * tg;
        as_[nt][0] = asrc[cc]; as_[nt][1] = asrc[cc + 1];
        ad_[nt][0] = adst[cc]; ad_[nt][1] = adst[cc + 1];
    }
#pragma unroll
    for (int half = 0; half < 2; half++) {
        int row = row0 + wid * 16 + g + half * 8;
        float ps = 0.f, pd = 0.f;
#pragma unroll
        for (int nt = 0; nt < 4; nt++) {
            ps += acc[nt][2*half] * as_[nt][0] + acc[nt][2*half+1] * as_[nt][1];
            pd += acc[nt][2*half] * ad_[nt][0] + acc[nt][2*half+1] * ad_[nt][1];
        }
        ps += __shfl_xor_sync(0xffffffffu, ps, 1);
        ps += __shfl_xor_sync(0xffffffffu, ps, 2);
        pd += __shfl_xor_sync(0xffffffffu, pd, 1);
        pd += __shfl_xor_sync(0xffffffffu, pd, 2);
        if (row < M) {
#pragma unroll
            for (int nt = 0; nt < 4; nt++) {
                int gc = nt * 8 + 2 * tg;
                float2 v = make_float2(acc[nt][half * 2], acc[nt][half * 2 + 1]);
                *reinterpret_cast<float2*>(&g_h2[(size_t)row * NCLASS + gc]) = v;
            }
            if (tg == 0) { g_ssrc2[row] = ps; g_sdst2[row] = pd; }
        }
    }
}

// ---------------- layer-2 fused softmax + aggregate (+b2 + 1e-6) ------------
__global__ void __launch_bounds__(256)
agg2_kernel(const float* __restrict__ b2, float* __restrict__ out) {
    __shared__ int   s_src[8][CAP];
    __shared__ float s_w[8][CAP];
    int w = threadIdx.x >> 5, lane = threadIdx.x & 31;
    int n = blockIdx.x * 8 + w;
    if (n >= NN) return;
    int r0 = g_rowptr[n], r1 = g_rowptr[n + 1], d = r1 - r0;
    float sdst = g_sdst2[n];

    if (d <= CAP) {
        float den = 0.f;
        for (int i = lane; i < d; i += 32) {
            int src = g_esrc[r0 + i];
            s_src[w][i] = src;
            float wv = __expf(lrelu(g_ssrc2[src] + sdst));
            s_w[w][i] = wv;
            den += wv;
        }
        den = warp_allsum(den);
        float inv = __frcp_rn(den + 1e-16f);
        __syncwarp();
        float acc = 0.f;
#pragma unroll 4
        for (int i = 0; i < d; i++) {
            acc = fmaf(s_w[w][i], g_h2[(size_t)s_src[w][i] * NCLASS + lane], acc);
        }
        out[(size_t)n * NCLASS + lane] = acc * inv + b2[lane] + 1e-6f;
    } else {
        float den = 0.f;
        for (int p = r0 + lane; p < r1; p += 32) {
            int src = g_esrc[p];
            float wv = __expf(lrelu(g_ssrc2[src] + sdst));
            g_w2[p] = wv; den += wv;
        }
        den = warp_allsum(den);
        float inv = __frcp_rn(den + 1e-16f);
        __threadfence_block();
        __syncwarp();
        float acc = 0.f;
        for (int p = r0; p < r1; p++)
            acc = fmaf(g_w2[p], g_h2[(size_t)g_esrc[p] * NCLASS + lane], acc);
        out[(size_t)n * NCLASS + lane] = acc * inv + b2[lane] + 1e-6f;
    }
}

// ---------------- launch ----------------------------------------------------
extern "C" void kernel_launch(void* const* d_in, const int* in_sizes, int n_in,
                              void* d_out, int out_size) {
    const float* x     = (const float*)d_in[0];
    const int*   ei    = (const int*)d_in[1];
    const float* W1    = (const float*)d_in[2];
    const float* asrc1 = (const float*)d_in[3];
    const float* adst1 = (const float*)d_in[4];
    const float* b1    = (const float*)d_in[5];
    const float* W2    = (const float*)d_in[6];
    const float* asrc2 = (const float*)d_in[7];
    const float* adst2 = (const float*)d_in[8];
    const float* b2    = (const float*)d_in[9];
    float* out = (float*)d_out;

    int N  = in_sizes[0] / F_IN;   // 50000
    int E  = in_sizes[1] / 2;      // 800000
    int ET = E + N;

    deg_init_kernel<<<SCAN_B, 256>>>();
    deg_count_kernel<<<(E + 255) / 256, 256>>>(ei, E);
    scan_p1<<<SCAN_B, 256>>>();
    scan_p2<<<1, 256>>>(SCAN_B);
    scan_p3<<<SCAN_B, 256>>>(N);
    fill_kernel<<<(ET + 255) / 256, 256>>>(ei, E, N);

    gemm1_kernel<<<dim3(F1 / 128, (N + 127) / 128), 256>>>(x, W1, asrc1, adst1);
    agg1_kernel<<<N, 256>>>(b1);

    gemm2_kernel<<<(N + 127) / 128, 256>>>(W2, asrc2, adst2);
    agg2_kernel<<<(N + 7) / 8, 256>>>(b2, out);
}

// round 6
// speedup vs baseline: 2.6406x; 1.0684x over previous
#include <cuda_runtime.h>
#include <cuda_bf16.h>
#include <math.h>

#define NN      50000
#define F_IN    512
#define F1      256
#define HEADS   8
#define HID     32
#define NCLASS  32
#define NEG_SLOPE 0.2f
#define ET_MAX  (800000 + NN)
#define CAP     128
#define SCAN_B  ((NN + 255) / 256)

// ---------------- scratch ----------------------------------------------------
__device__ float g_h1  [(size_t)NN * F1];
__device__ float g_agg1[(size_t)NN * F1];
__device__ float g_h2  [(size_t)NN * NCLASS];
__device__ float g_w1  [(size_t)HEADS * ET_MAX];  // fallback only
__device__ float g_w2  [(size_t)ET_MAX];          // fallback only
__device__ float g_ssrc1[NN * HEADS];
__device__ float g_sdst1[NN * HEADS];
__device__ float g_ssrc2[NN];
__device__ float g_sdst2[NN];
__device__ int g_deg   [NN];
__device__ int g_rowptr[NN + 1];
__device__ int g_cursor[NN];
__device__ int g_esrc  [ET_MAX];
__device__ int g_bsum  [256];
__device__ int g_boff  [256];

// ---------------- helpers ----------------------------------------------------
__device__ __forceinline__ float warp_allsum(float v) {
#pragma unroll
    for (int o = 16; o > 0; o >>= 1) v += __shfl_xor_sync(0xffffffffu, v, o);
    return v;
}
__device__ __forceinline__ float lrelu(float s) {
    return s > 0.f ? s : NEG_SLOPE * s;
}
__device__ __forceinline__ unsigned f2tf32(float f) {
    unsigned u;
    asm("cvt.rna.tf32.f32 %0, %1;" : "=r"(u) : "f"(f));
    return u;
}
__device__ __forceinline__ void mma_tf32(float* d, const unsigned* a, const unsigned* b) {
    asm volatile(
        "mma.sync.aligned.m16n8k8.row.col.f32.tf32.tf32.f32 "
        "{%0,%1,%2,%3}, {%4,%5,%6,%7}, {%8,%9}, {%0,%1,%2,%3};"
        : "+f"(d[0]), "+f"(d[1]), "+f"(d[2]), "+f"(d[3])
        : "r"(a[0]), "r"(a[1]), "r"(a[2]), "r"(a[3]), "r"(b[0]), "r"(b[1]));
}
__device__ __forceinline__ void cp_async16(void* smem, const void* gmem, int bytes) {
    unsigned s = (unsigned)__cvta_generic_to_shared(smem);
    asm volatile("cp.async.ca.shared.global [%0], [%1], 16, %2;"
                 :: "r"(s), "l"(gmem), "r"(bytes) : "memory");
}
#define CP_COMMIT() asm volatile("cp.async.commit_group;" ::: "memory")
#define CP_WAIT(n)  asm volatile("cp.async.wait_group %0;" :: "n"(n) : "memory")

// ---------------- CSR build --------------------------------------------------
__global__ void deg_init_kernel() {
    int i = blockIdx.x * blockDim.x + threadIdx.x;
    if (i < NN) { g_deg[i] = 1; g_cursor[i] = 0; }
}
__global__ void deg_count_kernel(const int* __restrict__ ei, int E) {
    int e = blockIdx.x * blockDim.x + threadIdx.x;
    if (e < E) atomicAdd(&g_deg[ei[E + e]], 1);
}
__global__ void scan_p1() {
    __shared__ int sh[256];
    int b = blockIdx.x, t = threadIdx.x;
    int i = b * 256 + t;
    int d = (i < NN) ? g_deg[i] : 0;
    int v = d;
    sh[t] = v; __syncthreads();
#pragma unroll
    for (int off = 1; off < 256; off <<= 1) {
        int u = (t >= off) ? sh[t - off] : 0;
        __syncthreads();
        v += u; sh[t] = v;
        __syncthreads();
    }
    if (i < NN) g_rowptr[i] = v;
    if (t == 255) g_bsum[b] = v;
}
__global__ void scan_p2(int nb) {
    __shared__ int sh[256];
    int t = threadIdx.x;
    int d = (t < nb) ? g_bsum[t] : 0;
    int v = d;
    sh[t] = v; __syncthreads();
#pragma unroll
    for (int off = 1; off < 256; off <<= 1) {
        int u = (t >= off) ? sh[t - off] : 0;
        __syncthreads();
        v += u; sh[t] = v;
        __syncthreads();
    }
    g_boff[t] = v - d;
}
__global__ void scan_p3(int N) {
    int i = blockIdx.x * 256 + threadIdx.x;
    if (i < N) {
        int incl = g_rowptr[i] + g_boff[blockIdx.x];
        g_rowptr[i] = incl - g_deg[i];
        if (i == N - 1) g_rowptr[N] = incl;
    }
}
__global__ void fill_kernel(const int* __restrict__ ei, int E, int N) {
    int idx = blockIdx.x * blockDim.x + threadIdx.x;
    int ET = E + N;
    if (idx >= ET) return;
    int src, dst;
    if (idx < E) { src = ei[idx]; dst = ei[E + idx]; } else { src = dst = idx - E; }
    int pos = g_rowptr[dst] + atomicAdd(&g_cursor[dst], 1);
    g_esrc[pos] = src;
}

// ---------------- GEMM1 (tf32, 128x256x16, 2-stage) + fused scores1 ---------
// 8 warps: warp_m = wid>>2 (2), warp_n = wid&3 (4). Warp tile 64x64.
#define AS_OFF 0
#define BS_OFF (2 * 128 * 20)
#define GEMM1_SMEM ((2 * 128 * 20 + 2 * 16 * 260) * 4)
__global__ void __launch_bounds__(256)
gemm1_kernel(const float* __restrict__ A, const float* __restrict__ B,
             const float* __restrict__ asrc, const float* __restrict__ adst) {
    extern __shared__ float sm[];
    float (*As)[128][20] = reinterpret_cast<float(*)[128][20]>(sm + AS_OFF);
    float (*Bs)[16][260] = reinterpret_cast<float(*)[16][260]>(sm + BS_OFF);

    const int M = NN, K = F_IN;
    int tid  = threadIdx.x;
    int lane = tid & 31, wid = tid >> 5;
    int warp_m = wid >> 2, warp_n = wid & 3;
    int row0 = blockIdx.x * 128;
    int g = lane >> 2, tg = lane & 3;

    float acc[4][8][4];
#pragma unroll
    for (int i = 0; i < 4; i++)
#pragma unroll
        for (int j = 0; j < 8; j++)
#pragma unroll
            for (int r = 0; r < 4; r++) acc[i][j][r] = 0.f;

    int a_r = tid >> 1, a_c = (tid & 1) * 8;
    int b_r = tid >> 4, b_c = (tid & 15) * 16;
    int gr = row0 + a_r;
    const float* a_base = A + (size_t)min(gr, M - 1) * K + a_c;
    int a_bytes = (gr < M) ? 16 : 0;
    const float* b_base = B + (size_t)b_r * F1 + b_c;

    cp_async16(&As[0][a_r][a_c],     a_base,     a_bytes);
    cp_async16(&As[0][a_r][a_c + 4], a_base + 4, a_bytes);
#pragma unroll
    for (int q = 0; q < 4; q++)
        cp_async16(&Bs[0][b_r][b_c + q * 4], b_base + q * 4, 16);
    CP_COMMIT();

    const int NT = K / 16;
    for (int kt = 0; kt < NT; kt++) {
        int buf = kt & 1;
        if (kt + 1 < NT) {
            int k1 = (kt + 1) * 16;
            cp_async16(&As[buf ^ 1][a_r][a_c],     a_base + k1,     a_bytes);
            cp_async16(&As[buf ^ 1][a_r][a_c + 4], a_base + k1 + 4, a_bytes);
#pragma unroll
            for (int q = 0; q < 4; q++)
                cp_async16(&Bs[buf ^ 1][b_r][b_c + q * 4],
                           b_base + (size_t)k1 * F1 + q * 4, 16);
            CP_COMMIT();
            CP_WAIT(1);
        } else {
            CP_WAIT(0);
        }
        __syncthreads();

#pragma unroll
        for (int ks = 0; ks < 2; ks++) {
            int kb = ks * 8;
            unsigned bfr[8][2];
#pragma unroll
            for (int nt = 0; nt < 8; nt++) {
                int nb = warp_n * 64 + nt * 8 + g;
                bfr[nt][0] = f2tf32(Bs[buf][kb + tg    ][nb]);
                bfr[nt][1] = f2tf32(Bs[buf][kb + tg + 4][nb]);
            }
#pragma unroll
            for (int mt = 0; mt < 4; mt++) {
                int rb = warp_m * 64 + mt * 16;
                unsigned afr[4];
                afr[0] = f2tf32(As[buf][rb + g    ][kb + tg    ]);
                afr[1] = f2tf32(As[buf][rb + g + 8][kb + tg    ]);
                afr[2] = f2tf32(As[buf][rb + g    ][kb + tg + 4]);
                afr[3] = f2tf32(As[buf][rb + g + 8][kb + tg + 4]);
#pragma unroll
                for (int nt = 0; nt < 8; nt++)
                    mma_tf32(acc[mt][nt], afr, bfr[nt]);
            }
        }
        __syncthreads();
    }

    // store h1
#pragma unroll
    for (int mt = 0; mt < 4; mt++) {
#pragma unroll
        for (int half = 0; half < 2; half++) {
            int grr = row0 + warp_m * 64 + mt * 16 + g + half * 8;
            if (grr >= M) continue;
#pragma unroll
            for (int nt = 0; nt < 8; nt++) {
                int gc = warp_n * 64 + nt * 8 + 2 * tg;
                float2 v = make_float2(acc[mt][nt][half * 2], acc[mt][nt][half * 2 + 1]);
                *reinterpret_cast<float2*>(&g_h1[(size_t)grr * F1 + gc]) = v;
            }
        }
    }

    // fused scores: warp covers 64 cols = heads h0, h0+1
    int h0 = warp_n * 2;
    float as_[8][2], ad_[8][2];
#pragma unroll
    for (int nt = 0; nt < 8; nt++) {
        int cc = warp_n * 64 + nt * 8 + 2 * tg;   // global col
        as_[nt][0] = asrc[cc]; as_[nt][1] = asrc[cc + 1];
        ad_[nt][0] = adst[cc]; ad_[nt][1] = adst[cc + 1];
    }
#pragma unroll
    for (int mt = 0; mt < 4; mt++) {
#pragma unroll
        for (int half = 0; half < 2; half++) {
            float ps0 = 0.f, pd0 = 0.f, ps1 = 0.f, pd1 = 0.f;
#pragma unroll
            for (int nt = 0; nt < 4; nt++) {
                ps0 += acc[mt][nt][2*half] * as_[nt][0] + acc[mt][nt][2*half+1] * as_[nt][1];
                pd0 += acc[mt][nt][2*half] * ad_[nt][0] + acc[mt][nt][2*half+1] * ad_[nt][1];
                ps1 += acc[mt][nt+4][2*half] * as_[nt+4][0] + acc[mt][nt+4][2*half+1] * as_[nt+4][1];
                pd1 += acc[mt][nt+4][2*half] * ad_[nt+4][0] + acc[mt][nt+4][2*half+1] * ad_[nt+4][1];
            }
            ps0 += __shfl_xor_sync(0xffffffffu, ps0, 1);
            ps0 += __shfl_xor_sync(0xffffffffu, ps0, 2);
            pd0 += __shfl_xor_sync(0xffffffffu, pd0, 1);
            pd0 += __shfl_xor_sync(0xffffffffu, pd0, 2);
            ps1 += __shfl_xor_sync(0xffffffffu, ps1, 1);
            ps1 += __shfl_xor_sync(0xffffffffu, ps1, 2);
            pd1 += __shfl_xor_sync(0xffffffffu, pd1, 1);
            pd1 += __shfl_xor_sync(0xffffffffu, pd1, 2);
            int row = row0 + warp_m * 64 + mt * 16 + g + half * 8;
            if (row < M && tg == 0) {
                g_ssrc1[row * HEADS + h0]     = ps0;
                g_sdst1[row * HEADS + h0]     = pd0;
                g_ssrc1[row * HEADS + h0 + 1] = ps1;
                g_sdst1[row * HEADS + h0 + 1] = pd1;
            }
        }
    }
}

// ---------------- layer-1 fused softmax + aggregate + ELU(+b1) --------------
__global__ void __launch_bounds__(256)
agg1_kernel(const float* __restrict__ b1) {
    __shared__ int   s_src[CAP];
    __shared__ float s_w[HEADS][CAP];
    int n = blockIdx.x;
    int tid = threadIdx.x, h = tid >> 5, lane = tid & 31;
    int r0 = g_rowptr[n], r1 = g_rowptr[n + 1], d = r1 - r0;
    float sdst = g_sdst1[n * HEADS + h];

    if (d <= CAP) {
        for (int p = tid; p < d; p += 256) s_src[p] = g_esrc[r0 + p];
        __syncthreads();
        float den = 0.f;
        for (int i = lane; i < d; i += 32) {
            int src = s_src[i];
            float w = __expf(lrelu(g_ssrc1[src * HEADS + h] + sdst));
            s_w[h][i] = w;
            den += w;
        }
        den = warp_allsum(den);
        float inv = __frcp_rn(den + 1e-16f);
        __syncwarp();
        float acc = 0.f;
#pragma unroll 4
        for (int i = 0; i < d; i++) {
            float a = s_w[h][i];
            int src = s_src[i];
            acc = fmaf(a, g_h1[(size_t)src * F1 + h * HID + lane], acc);
        }
        acc *= inv;
        float v = acc + b1[h * HID + lane];
        g_agg1[(size_t)n * F1 + h * HID + lane] = v > 0.f ? v : expm1f(v);
    } else {
        float* w1h = g_w1 + (size_t)h * ET_MAX;
        float den = 0.f;
        for (int p = r0 + lane; p < r1; p += 32) {
            int src = g_esrc[p];
            float w = __expf(lrelu(g_ssrc1[src * HEADS + h] + sdst));
            w1h[p] = w; den += w;
        }
        den = warp_allsum(den);
        float inv = __frcp_rn(den + 1e-16f);
        __threadfence_block();
        __syncwarp();
        float acc = 0.f;
        for (int p = r0; p < r1; p++) {
            int src = g_esrc[p];
            acc = fmaf(w1h[p], g_h1[(size_t)src * F1 + h * HID + lane], acc);
        }
        acc *= inv;
        float v = acc + b1[h * HID + lane];
        g_agg1[(size_t)n * F1 + h * HID + lane] = v > 0.f ? v : expm1f(v);
    }
}

// ---------------- GEMM2 (tf32, 128x32x16) + fused scores2 -------------------
__global__ void __launch_bounds__(256)
gemm2_kernel(const float* __restrict__ W2, const float* __restrict__ asrc,
             const float* __restrict__ adst) {
    __shared__ float As[2][128][20];
    __shared__ float Bs[2][16][36];

    const int M = NN, K = F1;
    int tid  = threadIdx.x;
    int lane = tid & 31, wid = tid >> 5;
    int row0 = blockIdx.x * 128;
    int g = lane >> 2, tg = lane & 3;

    float acc[4][4];
#pragma unroll
    for (int j = 0; j < 4; j++)
#pragma unroll
        for (int r = 0; r < 4; r++) acc[j][r] = 0.f;

    int a_r = tid >> 1, a_c = (tid & 1) * 8;
    int gr = row0 + a_r;
    const float* a_base = g_agg1 + (size_t)min(gr, M - 1) * K + a_c;
    int a_bytes = (gr < M) ? 16 : 0;
    int b_r = tid >> 3, b_c = (tid & 7) * 4;
    const float* b_base = W2 + (size_t)b_r * NCLASS + b_c;

    cp_async16(&As[0][a_r][a_c],     a_base,     a_bytes);
    cp_async16(&As[0][a_r][a_c + 4], a_base + 4, a_bytes);
    if (tid < 128) cp_async16(&Bs[0][b_r][b_c], b_base, 16);
    CP_COMMIT();

    const int NT = K / 16;
    for (int kt = 0; kt < NT; kt++) {
        int buf = kt & 1;
        if (kt + 1 < NT) {
            int k1 = (kt + 1) * 16;
            cp_async16(&As[buf ^ 1][a_r][a_c],     a_base + k1,     a_bytes);
            cp_async16(&As[buf ^ 1][a_r][a_c + 4], a_base + k1 + 4, a_bytes);
            if (tid < 128) cp_async16(&Bs[buf ^ 1][b_r][b_c],
                                      b_base + (size_t)k1 * NCLASS, 16);
            CP_COMMIT();
            CP_WAIT(1);
        } else {
            CP_WAIT(0);
        }
        __syncthreads();

#pragma unroll
        for (int ks = 0; ks < 2; ks++) {
            int kb = ks * 8;
            int rb = wid * 16;
            unsigned afr[4];
            afr[0] = f2tf32(As[buf][rb + g    ][kb + tg    ]);
            afr[1] = f2tf32(As[buf][rb + g + 8][kb + tg    ]);
            afr[2] = f2tf32(As[buf][rb + g    ][kb + tg + 4]);
            afr[3] = f2tf32(As[buf][rb + g + 8][kb + tg + 4]);
#pragma unroll
            for (int nt = 0; nt < 4; nt++) {
                int nb = nt * 8;
                unsigned bfr[2];
                bfr[0] = f2tf32(Bs[buf][kb + tg    ][nb + g]);
                bfr[1] = f2tf32(Bs[buf][kb + tg + 4][nb + g]);
                mma_tf32(acc[nt], afr, bfr);
            }
        }
        __syncthreads();
    }

    float as_[4][2], ad_[4][2];
#pragma unroll
    for (int nt = 0; nt < 4; nt++) {
        int cc = nt * 8 + 2 * tg;
        as_[nt][0] = asrc[cc]; as_[nt][1] = asrc[cc + 1];
        ad_[nt][0] = adst[cc]; ad_[nt][1] = adst[cc + 1];
    }
#pragma unroll
    for (int half = 0; half < 2; half++) {
        int row = row0 + wid * 16 + g + half * 8;
        float ps = 0.f, pd = 0.f;
#pragma unroll
        for (int nt = 0; nt < 4; nt++) {
            ps += acc[nt][2*half] * as_[nt][0] + acc[nt][2*half+1] * as_[nt][1];
            pd += acc[nt][2*half] * ad_[nt][0] + acc[nt][2*half+1] * ad_[nt][1];
        }
        ps += __shfl_xor_sync(0xffffffffu, ps, 1);
        ps += __shfl_xor_sync(0xffffffffu, ps, 2);
        pd += __shfl_xor_sync(0xffffffffu, pd, 1);
        pd += __shfl_xor_sync(0xffffffffu, pd, 2);
        if (row < M) {
#pragma unroll
            for (int nt = 0; nt < 4; nt++) {
                int gc = nt * 8 + 2 * tg;
                float2 v = make_float2(acc[nt][half * 2], acc[nt][half * 2 + 1]);
                *reinterpret_cast<float2*>(&g_h2[(size_t)row * NCLASS + gc]) = v;
            }
            if (tg == 0) { g_ssrc2[row] = ps; g_sdst2[row] = pd; }
        }
    }
}

// ---------------- layer-2 fused softmax + aggregate (+b2 + 1e-6) ------------
__global__ void __launch_bounds__(256)
agg2_kernel(const float* __restrict__ b2, float* __restrict__ out) {
    __shared__ int   s_src[8][CAP];
    __shared__ float s_w[8][CAP];
    int w = threadIdx.x >> 5, lane = threadIdx.x & 31;
    int n = blockIdx.x * 8 + w;
    if (n >= NN) return;
    int r0 = g_rowptr[n], r1 = g_rowptr[n + 1], d = r1 - r0;
    float sdst = g_sdst2[n];

    if (d <= CAP) {
        float den = 0.f;
        for (int i = lane; i < d; i += 32) {
            int src = g_esrc[r0 + i];
            s_src[w][i] = src;
            float wv = __expf(lrelu(g_ssrc2[src] + sdst));
            s_w[w][i] = wv;
            den += wv;
        }
        den = warp_allsum(den);
        float inv = __frcp_rn(den + 1e-16f);
        __syncwarp();
        float acc = 0.f;
#pragma unroll 4
        for (int i = 0; i < d; i++) {
            acc = fmaf(s_w[w][i], g_h2[(size_t)s_src[w][i] * NCLASS + lane], acc);
        }
        out[(size_t)n * NCLASS + lane] = acc * inv + b2[lane] + 1e-6f;
    } else {
        float den = 0.f;
        for (int p = r0 + lane; p < r1; p += 32) {
            int src = g_esrc[p];
            float wv = __expf(lrelu(g_ssrc2[src] + sdst));
            g_w2[p] = wv; den += wv;
        }
        den = warp_allsum(den);
        float inv = __frcp_rn(den + 1e-16f);
        __threadfence_block();
        __syncwarp();
        float acc = 0.f;
        for (int p = r0; p < r1; p++)
            acc = fmaf(g_w2[p], g_h2[(size_t)g_esrc[p] * NCLASS + lane], acc);
        out[(size_t)n * NCLASS + lane] = acc * inv + b2[lane] + 1e-6f;
    }
}

// ---------------- launch ----------------------------------------------------
extern "C" void kernel_launch(void* const* d_in, const int* in_sizes, int n_in,
                              void* d_out, int out_size) {
    const float* x     = (const float*)d_in[0];
    const int*   ei    = (const int*)d_in[1];
    const float* W1    = (const float*)d_in[2];
    const float* asrc1 = (const float*)d_in[3];
    const float* adst1 = (const float*)d_in[4];
    const float* b1    = (const float*)d_in[5];
    const float* W2    = (const float*)d_in[6];
    const float* asrc2 = (const float*)d_in[7];
    const float* adst2 = (const float*)d_in[8];
    const float* b2    = (const float*)d_in[9];
    float* out = (float*)d_out;

    int N  = in_sizes[0] / F_IN;   // 50000
    int E  = in_sizes[1] / 2;      // 800000
    int ET = E + N;

    cudaFuncSetAttribute(gemm1_kernel,
                         cudaFuncAttributeMaxDynamicSharedMemorySize, GEMM1_SMEM);

    // fork: CSR build on side stream, gemm1 concurrently on main stream
    cudaStream_t s2;
    cudaStreamCreateWithFlags(&s2, cudaStreamNonBlocking);
    cudaEvent_t ev0, ev1;
    cudaEventCreateWithFlags(&ev0, cudaEventDisableTiming);
    cudaEventCreateWithFlags(&ev1, cudaEventDisableTiming);

    cudaEventRecord(ev0, 0);
    cudaStreamWaitEvent(s2, ev0, 0);

    deg_init_kernel<<<SCAN_B, 256, 0, s2>>>();                       // launch 1
    deg_count_kernel<<<(E + 255) / 256, 256, 0, s2>>>(ei, E);        // launch 2
    scan_p1<<<SCAN_B, 256, 0, s2>>>();                               // launch 3

    gemm1_kernel<<<(N + 127) / 128, 256, GEMM1_SMEM>>>(              // launch 4 (profiled)
        x, W1, asrc1, adst1);

    scan_p2<<<1, 256, 0, s2>>>(SCAN_B);
    scan_p3<<<SCAN_B, 256, 0, s2>>>(N);
    fill_kernel<<<(ET + 255) / 256, 256, 0, s2>>>(ei, E, N);
    cudaEventRecord(ev1, s2);
    cudaStreamWaitEvent(0, ev1, 0);

    agg1_kernel<<<N, 256>>>(b1);
    gemm2_kernel<<<(N + 127) / 128, 256>>>(W2, asrc2, adst2);
    agg2_kernel<<<(N + 7) / 8, 256>>>(b2, out);
}